// round 14
// baseline (speedup 1.0000x reference)
#include <cuda_runtime.h>
#include <cuda_fp16.h>
#include <cstdint>

#define H 128
#define B_MAX 256
#define QGPB 16                 // graphs per q-block

// ---------------- PTX helpers ----------------
__device__ __forceinline__ uint32_t smem_u32(const void* p) {
    uint32_t a;
    asm("{ .reg .u64 t; cvta.to.shared.u64 t, %1; cvt.u32.u64 %0, t; }" : "=r"(a) : "l"(p));
    return a;
}
__device__ __forceinline__ void ldsm4(uint32_t r[4], uint32_t addr) {
    asm volatile("ldmatrix.sync.aligned.m8n8.x4.shared.b16 {%0,%1,%2,%3}, [%4];"
        : "=r"(r[0]), "=r"(r[1]), "=r"(r[2]), "=r"(r[3]) : "r"(addr));
}
__device__ __forceinline__ void mma16816(float c[4], const uint32_t a[4], const uint32_t b[2]) {
    asm volatile("mma.sync.aligned.m16n8k16.row.col.f32.f16.f16.f32 "
        "{%0,%1,%2,%3}, {%4,%5,%6,%7}, {%8,%9}, {%0,%1,%2,%3};"
        : "+f"(c[0]), "+f"(c[1]), "+f"(c[2]), "+f"(c[3])
        : "r"(a[0]), "r"(a[1]), "r"(a[2]), "r"(a[3]), "r"(b[0]), "r"(b[1]));
}
__device__ __forceinline__ uint32_t pack_h2(float a, float b) {
    __half2 h = __floats2half2_rn(a, b);
    return *reinterpret_cast<uint32_t*>(&h);
}
#define MBARRIER_INIT(mbar, cnt) \
    asm volatile("mbarrier.init.shared.b64 [%0], %1;" :: "r"((uint32_t)(mbar)), "r"((uint32_t)(cnt)) : "memory")
#define MBARRIER_WAIT_PARITY(mbar, parity) do { \
    uint32_t _m = (uint32_t)(mbar), _p = (uint32_t)(parity), _d; \
    asm volatile("{\n\t.reg .pred p;\n\tmbarrier.try_wait.parity.acquire.cta.shared::cta.b64 p, [%1], %2;\n\tselp.b32 %0, 1, 0, p;\n\t}" \
        : "=r"(_d) : "r"(_m), "r"(_p) : "memory"); \
    if (!_d) { \
        asm volatile("{\n\t.reg .pred P1;\n\tWL_%=:\n\tmbarrier.try_wait.parity.acquire.cta.shared::cta.b64 P1, [%0], %1, 0x989680;\n\t@P1 bra.uni WD_%=;\n\tbra.uni WL_%=;\n\tWD_%=:\n\t}" \
            :: "r"(_m), "r"(_p) : "memory"); \
    } \
} while (0)

// ---------------------------------------------------------------------------
// One fused kernel (512 threads = 16 warps, occ 1).
// Blocks [0, B): full attention for graph b. Blocks [B, B+qb): q GEMM.
// Attn warp (mi = wid>>2, ni = wid&3) owns rows [32mi,+32) x cols [32ni,+32).
// A: full-tile TMA bulk, double raw buffer, simple convert.
// B (Wk) fragments loaded ONCE from global into registers (no smem B traffic).
// ---------------------------------------------------------------------------
#define THREADS 512
#define RS 272                  // fp16 A tile row stride (bytes), conflict-free
#define SM_RAW0 0               // raw fp32 tile buf0: 128 x 512B
#define SM_RAW1 65536
#define SM_AH   131072          // fp16 A tile: 128 x 272 = 34816
#define SM_BKWM 165888          // bk_s[128] + wm_s[128] f32 = 1024
#define SM_SCP  166912          // score partials [4][128] f32 (o_part reuse)
#define SM_RED  168960          // red[4] f32
#define SM_BND  168976          // bounds[2] int
#define SM_MB   168984          // 2 mbarriers
#define SM_TOTAL 169088

__device__ __forceinline__ void issue_tile_tma(uint32_t sb, const float* prot,
                                               int t0, int nvalid, int buf) {
    uint32_t dst = sb + (buf ? SM_RAW1 : SM_RAW0);
    uint32_t mb  = sb + SM_MB + buf * 8;
    uint32_t bytes = (uint32_t)nvalid * 512u;
    const void* src = (const void*)(prot + (size_t)t0 * H);
    asm volatile("mbarrier.arrive.expect_tx.shared.b64 _, [%0], %1;"
                 :: "r"(mb), "r"(bytes) : "memory");
    asm volatile("cp.async.bulk.shared::cta.global.mbarrier::complete_tx::bytes "
                 "[%0], [%1], %2, [%3];"
                 :: "r"(dst), "l"(src), "r"(bytes), "r"(mb) : "memory");
}

__global__ __launch_bounds__(THREADS, 1)
void fused_kernel(const float* __restrict__ prot,
                  const float* __restrict__ Wk,
                  const float* __restrict__ bk,
                  const float* __restrict__ Wm,
                  const int*   __restrict__ bwords,
                  const float* __restrict__ mol,
                  const float* __restrict__ Wq,
                  const float* __restrict__ bq,
                  float* __restrict__ out,
                  int N, int B) {
    extern __shared__ char smem[];
    const int t   = threadIdx.x;
    const int bid = blockIdx.x;

    // ================= q blocks =================
    if (bid >= B) {
        float* wq_s  = (float*)smem;                 // [128][129]
        float* mol_s = (float*)smem + 128 * 129;     // [QGPB][128]
        const int g0 = (bid - B) * QGPB;
        const float4* WqV = (const float4*)Wq;
#pragma unroll
        for (int i = 0; i < 8; ++i) {
            int idx = t + i * THREADS;               // 0..4095 float4s
            int h = idx >> 5, j4 = idx & 31;
            float4 v = WqV[idx];
            wq_s[h * 129 + 4 * j4 + 0] = v.x;
            wq_s[h * 129 + 4 * j4 + 1] = v.y;
            wq_s[h * 129 + 4 * j4 + 2] = v.z;
            wq_s[h * 129 + 4 * j4 + 3] = v.w;
        }
#pragma unroll
        for (int i = 0; i < 4; ++i) {
            int idx = t + i * THREADS;               // 0..2047
            int g = idx >> 7;
            mol_s[idx] = (g0 + g < B) ? mol[(size_t)(g0 + g) * H + (idx & 127)] : 0.f;
        }
        __syncthreads();
#pragma unroll
        for (int p = 0; p < 4; ++p) {
            int idx = t + p * THREADS;               // 0..2047
            int g = idx >> 7, h = idx & 127;
            const float* ms = mol_s + g * 128;
            const float* wr = wq_s + h * 129;
            float acc = bq[h];
#pragma unroll 8
            for (int j = 0; j < H; ++j) acc = fmaf(ms[j], wr[j], acc);
            if (g0 + g < B)
                out[(size_t)(B + g0 + g) * H + h] = fmaxf(acc, 0.f);
        }
        return;
    }

    // ================= attention blocks =================
    const uint32_t sb = smem_u32(smem);
    float* bk_s  = (float*)(smem + SM_BKWM);
    float* wm_s  = (float*)(smem + SM_BKWM) + 128;
    float* scp   = (float*)(smem + SM_SCP);
    float* red_s = (float*)(smem + SM_RED);
    int*   bnd_s = (int*)(smem + SM_BND);

    const int wid = t >> 5;
    const int l   = t & 31;
    const int mi  = wid >> 2;        // 0..3 : 32-row group
    const int ni  = wid & 3;         // 0..3 : 32-col group
    const int b   = bid;

    if (t == 0) {
        MBARRIER_INIT(sb + SM_MB, 1);
        MBARRIER_INIT(sb + SM_MB + 8, 1);
    }
    if (t >= 32 && t < 160)  bk_s[t - 32]  = bk[t - 32];
    if (t >= 160 && t < 288) wm_s[t - 160] = Wm[t - 160];

    // warps 0,1: 32-ary lower_bound for seg bounds (b, b+1)
    if (wid < 2) {
        int z = bwords[N - 1] | bwords[N - 3] | bwords[N - 9] | bwords[N - 33];
        const bool is64 = (z == 0);
        const long long* b64 = (const long long*)bwords;
        const long long v = (long long)(b + wid);
        int lo = 0, hi = N;
        while (hi - lo > 32) {
            long long span = hi - lo;
            int pos = lo + (int)((span * (l + 1)) / 33);
            long long x = is64 ? b64[pos] : (long long)bwords[pos];
            unsigned m = __ballot_sync(0xffffffffu, x < v);
            int c = __popc(m);
            int nlo = (c == 0)  ? lo : lo + (int)((span * c) / 33);
            int nhi = (c == 32) ? hi : lo + (int)((span * (c + 1)) / 33);
            lo = nlo; hi = nhi;
        }
        int pos = lo + l;
        long long x = (pos < hi) ? (is64 ? b64[pos] : (long long)bwords[pos])
                                 : 0x7fffffffffffffffLL;
        unsigned m = __ballot_sync(0xffffffffu, x < v);
        if (l == 0) bnd_s[wid] = lo + __popc(m);
    }

    // ---- B (Wk) fragments for this warp's 32 cols, hi fp16, in registers.
    //      One-time global load; Wk is 64KB and L2-hot across all CTAs. ----
    uint32_t bh[8][4][2];
#pragma unroll
    for (int kt = 0; kt < 8; ++kt)
#pragma unroll
        for (int nt = 0; nt < 4; ++nt) {
            int n = ni * 32 + nt * 8 + (l >> 2);
            const float2* p = (const float2*)(Wk + (size_t)n * H + kt * 16 + 2 * (l & 3));
            float2 v0 = p[0];   // k, k+1
            float2 v1 = p[4];   // k+8, k+9
            bh[kt][nt][0] = pack_h2(v0.x, v0.y);
            bh[kt][nt][1] = pack_h2(v1.x, v1.y);
        }
    __syncthreads();                             // bounds + bk/wm + mbars ready

    const int lo = bnd_s[0], hi = bnd_s[1];
    const int rows = hi - lo;

    if (rows <= 0) {                             // empty graph
        if (t < H) out[(size_t)b * H + t] = 0.f;
        return;
    }

    const int ntiles = (rows + 127) >> 7;

    // prefetch tiles 0 and 1 via TMA bulk
    if (t == 0) {
        issue_tile_tma(sb, prot, lo, min(128, rows), 0);
        if (ntiles > 1)
            issue_tile_tma(sb, prot, lo + 128, min(128, rows - 128), 1);
    }

    // lane-static addresses
    const uint32_t laneByte = (uint32_t)(((l & 7) + ((l >> 3) & 1) * 8) * RS + ((l >> 4) << 4));
    const uint32_t aWarp = sb + SM_AH + (uint32_t)(mi * 32 * RS) + laneByte;
    const int tR = t >> 5;      // convert row base
    const int tJ = t & 31;      // convert float4 col

    float o_acc[4][2];
#pragma unroll
    for (int nt = 0; nt < 4; ++nt) { o_acc[nt][0] = 0.f; o_acc[nt][1] = 0.f; }
    float d_loc = 0.f;

    for (int i = 0; i < ntiles; ++i) {
        const int nvalid = min(128, rows - i * 128);
        const int buf = i & 1;
        const uint32_t rawOff = buf ? SM_RAW1 : SM_RAW0;

        // ---- wait TMA; convert fp32 -> fp16 AH (zeros for rows >= nvalid) ----
        MBARRIER_WAIT_PARITY(sb + SM_MB + buf * 8, (i >> 1) & 1);
#pragma unroll
        for (int it = 0; it < 8; ++it) {
            int r = tR + it * 16;
            uint2 u = make_uint2(0u, 0u);
            if (r < nvalid) {
                float4 v = *(const float4*)(smem + rawOff + r * 512 + tJ * 16);
                u.x = pack_h2(v.x, v.y);
                u.y = pack_h2(v.z, v.w);
            }
            *(uint2*)(smem + SM_AH + r * RS + tJ * 8) = u;
        }
        __syncthreads();                         // S1: AH ready, RAW[buf] free

        if (t == 0 && i + 2 < ntiles) {
            int t2 = lo + (i + 2) * 128;
            issue_tile_tma(sb, prot, t2, min(128, rows - (i + 2) * 128), buf);
        }

        // ---- single-pass fp16 MMA: A from smem (ldsm), B from registers ----
        float acc[2][4][4];
#pragma unroll
        for (int mt = 0; mt < 2; ++mt)
#pragma unroll
            for (int nt = 0; nt < 4; ++nt)
#pragma unroll
                for (int i2 = 0; i2 < 4; ++i2) acc[mt][nt][i2] = 0.f;

#pragma unroll
        for (int kt = 0; kt < 8; ++kt) {
#pragma unroll
            for (int mt = 0; mt < 2; ++mt) {
                uint32_t ah[4];
                ldsm4(ah, aWarp + (uint32_t)(mt * 16 * RS + kt * 32));
#pragma unroll
                for (int nt = 0; nt < 4; ++nt)
                    mma16816(acc[mt][nt], ah, bh[kt][nt]);
            }
        }

        // ---- relu + bias (from smem); score partials ----
#pragma unroll
        for (int mt = 0; mt < 2; ++mt) {
            float s0 = 0.f, s1 = 0.f;
#pragma unroll
            for (int nt = 0; nt < 4; ++nt) {
                int c = ni * 32 + nt * 8 + 2 * (l & 3);
                float2 bkv = *(const float2*)(bk_s + c);
                float2 wmv = *(const float2*)(wm_s + c);
                acc[mt][nt][0] = fmaxf(acc[mt][nt][0] + bkv.x, 0.f);
                acc[mt][nt][1] = fmaxf(acc[mt][nt][1] + bkv.y, 0.f);
                acc[mt][nt][2] = fmaxf(acc[mt][nt][2] + bkv.x, 0.f);
                acc[mt][nt][3] = fmaxf(acc[mt][nt][3] + bkv.y, 0.f);
                s0 = fmaf(acc[mt][nt][0], wmv.x, s0);
                s0 = fmaf(acc[mt][nt][1], wmv.y, s0);
                s1 = fmaf(acc[mt][nt][2], wmv.x, s1);
                s1 = fmaf(acc[mt][nt][3], wmv.y, s1);
            }
#pragma unroll
            for (int o = 1; o <= 2; o <<= 1) {
                s0 += __shfl_xor_sync(0xffffffffu, s0, o);
                s1 += __shfl_xor_sync(0xffffffffu, s1, o);
            }
            if ((l & 3) == 0) {
                int row = mi * 32 + mt * 16 + (l >> 2);
                scp[ni * 128 + row]     = s0;
                scp[ni * 128 + row + 8] = s1;
            }
        }
        __syncthreads();                         // S2: scp ready; MMA reads of AH done

        // ---- per-warp exp from scp (no extra sync) ----
        float e_lo[2], e_hi[2];
#pragma unroll
        for (int mt = 0; mt < 2; ++mt) {
            int row = mi * 32 + mt * 16 + (l >> 2);
            float sA = scp[row] + scp[128 + row] + scp[256 + row] + scp[384 + row];
            float sB = scp[row + 8] + scp[128 + row + 8] + scp[256 + row + 8] + scp[384 + row + 8];
            e_lo[mt] = (row < nvalid) ? __expf(sA) : 0.f;
            e_hi[mt] = (row + 8 < nvalid) ? __expf(sB) : 0.f;
        }
        if (ni == 0 && (l & 3) == 0)
            d_loc += e_lo[0] + e_hi[0] + e_lo[1] + e_hi[1];

        // ---- o partial accumulation (k in regs) ----
#pragma unroll
        for (int mt = 0; mt < 2; ++mt)
#pragma unroll
            for (int nt = 0; nt < 4; ++nt) {
                o_acc[nt][0] = fmaf(e_lo[mt], acc[mt][nt][0], o_acc[nt][0]);
                o_acc[nt][0] = fmaf(e_hi[mt], acc[mt][nt][2], o_acc[nt][0]);
                o_acc[nt][1] = fmaf(e_lo[mt], acc[mt][nt][1], o_acc[nt][1]);
                o_acc[nt][1] = fmaf(e_hi[mt], acc[mt][nt][3], o_acc[nt][1]);
            }
    }

    // ---- final reductions & direct output write ----
    __syncthreads();                             // scp free; reuse as o_part[4][128]
#pragma unroll
    for (int nt = 0; nt < 4; ++nt)
#pragma unroll
        for (int o = 4; o <= 16; o <<= 1) {
            o_acc[nt][0] += __shfl_xor_sync(0xffffffffu, o_acc[nt][0], o);
            o_acc[nt][1] += __shfl_xor_sync(0xffffffffu, o_acc[nt][1], o);
        }
    if ((l >> 2) == 0) {                         // lanes 0..3
#pragma unroll
        for (int nt = 0; nt < 4; ++nt) {
            int c = ni * 32 + nt * 8 + 2 * l;
            scp[mi * 128 + c]     = o_acc[nt][0];
            scp[mi * 128 + c + 1] = o_acc[nt][1];
        }
    }
    // d reduction: nonzero only in ni==0 warps
    {
#pragma unroll
        for (int o = 16; o; o >>= 1) d_loc += __shfl_xor_sync(0xffffffffu, d_loc, o);
        if (ni == 0 && l == 0) red_s[mi] = d_loc;
    }
    __syncthreads();
    if (t < 128) {
        float d = red_s[0] + red_s[1] + red_s[2] + red_s[3];
        float o = scp[t] + scp[128 + t] + scp[256 + t] + scp[384 + t];
        out[(size_t)b * H + t] = (d > 0.f) ? (o / d) : 0.f;
    }
}

// ---------------------------------------------------------------------------
extern "C" void kernel_launch(void* const* d_in, const int* in_sizes, int n_in,
                              void* d_out, int out_size) {
    const float* mol   = (const float*)d_in[0];
    const float* prot  = (const float*)d_in[1];
    const int*   batch = (const int*)d_in[2];
    const float* Wq    = (const float*)d_in[3];
    const float* bq    = (const float*)d_in[4];
    const float* Wk    = (const float*)d_in[5];
    const float* bk    = (const float*)d_in[6];
    const float* Wm    = (const float*)d_in[7];
    float* out = (float*)d_out;

    int B = in_sizes[0] / H;   // 256
    int N = in_sizes[1] / H;   // 262144
    int qb = (B + QGPB - 1) / QGPB;

    cudaFuncSetAttribute(fused_kernel, cudaFuncAttributeMaxDynamicSharedMemorySize, SM_TOTAL);
    fused_kernel<<<B + qb, THREADS, SM_TOTAL>>>(
        prot, Wk, bk, Wm, batch, mol, Wq, bq, out, N, B);
}

// round 15
// speedup vs baseline: 1.2515x; 1.2515x over previous
#include <cuda_runtime.h>
#include <cuda_fp16.h>
#include <cstdint>

#define H 128
#define B_MAX 256
#define QGPB 16                 // graphs per q-block

// ---------------- PTX helpers ----------------
__device__ __forceinline__ uint32_t smem_u32(const void* p) {
    uint32_t a;
    asm("{ .reg .u64 t; cvta.to.shared.u64 t, %1; cvt.u32.u64 %0, t; }" : "=r"(a) : "l"(p));
    return a;
}
__device__ __forceinline__ void ldsm4(uint32_t r[4], uint32_t addr) {
    asm volatile("ldmatrix.sync.aligned.m8n8.x4.shared.b16 {%0,%1,%2,%3}, [%4];"
        : "=r"(r[0]), "=r"(r[1]), "=r"(r[2]), "=r"(r[3]) : "r"(addr));
}
__device__ __forceinline__ void mma16816(float c[4], const uint32_t a[4], const uint32_t b[2]) {
    asm volatile("mma.sync.aligned.m16n8k16.row.col.f32.f16.f16.f32 "
        "{%0,%1,%2,%3}, {%4,%5,%6,%7}, {%8,%9}, {%0,%1,%2,%3};"
        : "+f"(c[0]), "+f"(c[1]), "+f"(c[2]), "+f"(c[3])
        : "r"(a[0]), "r"(a[1]), "r"(a[2]), "r"(a[3]), "r"(b[0]), "r"(b[1]));
}
__device__ __forceinline__ uint32_t pack_h2(float a, float b) {
    __half2 h = __floats2half2_rn(a, b);
    return *reinterpret_cast<uint32_t*>(&h);
}
#define MBARRIER_INIT(mbar, cnt) \
    asm volatile("mbarrier.init.shared.b64 [%0], %1;" :: "r"((uint32_t)(mbar)), "r"((uint32_t)(cnt)) : "memory")
#define MBARRIER_ARRIVE(mbar) \
    asm volatile("mbarrier.arrive.shared.b64 _, [%0];" :: "r"((uint32_t)(mbar)) : "memory")
#define MBARRIER_WAIT_PARITY(mbar, parity) do { \
    uint32_t _m = (uint32_t)(mbar), _p = (uint32_t)(parity), _d; \
    asm volatile("{\n\t.reg .pred p;\n\tmbarrier.try_wait.parity.acquire.cta.shared::cta.b64 p, [%1], %2;\n\tselp.b32 %0, 1, 0, p;\n\t}" \
        : "=r"(_d) : "r"(_m), "r"(_p) : "memory"); \
    if (!_d) { \
        asm volatile("{\n\t.reg .pred P1;\n\tWL_%=:\n\tmbarrier.try_wait.parity.acquire.cta.shared::cta.b64 P1, [%0], %1, 0x989680;\n\t@P1 bra.uni WD_%=;\n\tbra.uni WL_%=;\n\tWD_%=:\n\t}" \
            :: "r"(_m), "r"(_p) : "memory"); \
    } \
} while (0)
#define BAR_CONS() asm volatile("bar.sync 1, 256;" ::: "memory")
#define BAR_PROD() asm volatile("bar.sync 2, 256;" ::: "memory")

// ---------------------------------------------------------------------------
// One fused kernel (512 threads), warp-specialized.
// Blocks [0, BA): attention for graphs 2b and 2b+1 (one contiguous row range
//   with one boundary; two (o,d) accumulator banks).
//   Threads 0-255 = 8 consumer warps (MMA+epilogue),
//   threads 256-511 = 8 producer warps (TMA wait + fp32->fp16 convert).
// Blocks [BA, BA+qb): q GEMM.
// ---------------------------------------------------------------------------
#define THREADS 512
#define RS 272                  // fp16 A tile row stride (bytes)
#define SM_RAW  0               // raw fp32 tile: 128 x 512B = 65536 (single)
#define SM_AH0  65536           // fp16 A tile buf0: 34816
#define SM_AH1  100352          // fp16 A tile buf1: 34816
#define SM_WK   135168          // fp16 Wk tile: 34816
#define SM_BKWM 169984          // bk_s[128] + wm_s[128]
#define SM_SCP0 171008          // score partials buf0 [4][128]
#define SM_SCP1 173056          // score partials buf1
#define SM_ES0  175104          // e buf0 [128]
#define SM_ES1  175616          // e buf1
#define SM_RED  176128          // red0[4], red1[4]
#define SM_BND  176192          // bounds[3] int
#define SM_MB   176208          // tma(8) full0(8) full1(8) empty0(8) empty1(8)
#define SM_TOTAL 176256

__device__ __forceinline__ void issue_tma(uint32_t sb, const float* prot,
                                          int grow0, int nvalid) {
    uint32_t mb = sb + SM_MB;
    uint32_t bytes = (uint32_t)nvalid * 512u;
    const void* src = (const void*)(prot + (size_t)grow0 * H);
    asm volatile("mbarrier.arrive.expect_tx.shared.b64 _, [%0], %1;"
                 :: "r"(mb), "r"(bytes) : "memory");
    asm volatile("cp.async.bulk.shared::cta.global.mbarrier::complete_tx::bytes "
                 "[%0], [%1], %2, [%3];"
                 :: "r"(sb + SM_RAW), "l"(src), "r"(bytes), "r"(mb) : "memory");
}

__global__ __launch_bounds__(THREADS, 1)
void fused_kernel(const float* __restrict__ prot,
                  const float* __restrict__ Wk,
                  const float* __restrict__ bk,
                  const float* __restrict__ Wm,
                  const int*   __restrict__ bwords,
                  const float* __restrict__ mol,
                  const float* __restrict__ Wq,
                  const float* __restrict__ bq,
                  float* __restrict__ out,
                  int N, int B, int BA) {
    extern __shared__ char smem[];
    const int t   = threadIdx.x;
    const int bid = blockIdx.x;

    // ================= q blocks =================
    if (bid >= BA) {
        float* wq_s  = (float*)smem;                 // [128][129]
        float* mol_s = (float*)smem + 128 * 129;     // [QGPB][128]
        const int g0 = (bid - BA) * QGPB;
        const float4* WqV = (const float4*)Wq;
#pragma unroll
        for (int i = 0; i < 8; ++i) {
            int idx = t + i * THREADS;
            int h = idx >> 5, j4 = idx & 31;
            float4 v = WqV[idx];
            wq_s[h * 129 + 4 * j4 + 0] = v.x;
            wq_s[h * 129 + 4 * j4 + 1] = v.y;
            wq_s[h * 129 + 4 * j4 + 2] = v.z;
            wq_s[h * 129 + 4 * j4 + 3] = v.w;
        }
#pragma unroll
        for (int i = 0; i < 4; ++i) {
            int idx = t + i * THREADS;
            int g = idx >> 7;
            mol_s[idx] = (g0 + g < B) ? mol[(size_t)(g0 + g) * H + (idx & 127)] : 0.f;
        }
        __syncthreads();
#pragma unroll
        for (int p = 0; p < 4; ++p) {
            int idx = t + p * THREADS;
            int g = idx >> 7, h = idx & 127;
            const float* ms = mol_s + g * 128;
            const float* wr = wq_s + h * 129;
            float acc = bq[h];
#pragma unroll 8
            for (int j = 0; j < H; ++j) acc = fmaf(ms[j], wr[j], acc);
            if (g0 + g < B)
                out[(size_t)(B + g0 + g) * H + h] = fmaxf(acc, 0.f);
        }
        return;
    }

    // ================= attention blocks =================
    const uint32_t sb = smem_u32(smem);
    float* bk_s  = (float*)(smem + SM_BKWM);
    float* wm_s  = (float*)(smem + SM_BKWM) + 128;
    float* red_s = (float*)(smem + SM_RED);
    int*   bnd_s = (int*)(smem + SM_BND);

    const int wid = t >> 5;
    const int l   = t & 31;
    const int g0 = bid * 2;                      // first graph of the pair

    if (t == 0) {
        MBARRIER_INIT(sb + SM_MB, 1);            // tma
        MBARRIER_INIT(sb + SM_MB + 8, 256);      // full0
        MBARRIER_INIT(sb + SM_MB + 16, 256);     // full1
        MBARRIER_INIT(sb + SM_MB + 24, 256);     // empty0
        MBARRIER_INIT(sb + SM_MB + 32, 256);     // empty1
    }
    if (t >= 128 && t < 256) bk_s[t - 128] = bk[t - 128];
    if (t >= 256 && t < 384) wm_s[t - 256] = Wm[t - 256];

    // warps 0..2: 32-ary lower_bound for g0, g0+1, g0+2
    if (wid < 3) {
        int z = bwords[N - 1] | bwords[N - 3] | bwords[N - 9] | bwords[N - 33];
        const bool is64 = (z == 0);
        const long long* b64 = (const long long*)bwords;
        const long long v = (long long)(g0 + wid);
        int lo = 0, hi = N;
        while (hi - lo > 32) {
            long long span = hi - lo;
            int pos = lo + (int)((span * (l + 1)) / 33);
            long long x = is64 ? b64[pos] : (long long)bwords[pos];
            unsigned m = __ballot_sync(0xffffffffu, x < v);
            int c = __popc(m);
            int nlo = (c == 0)  ? lo : lo + (int)((span * c) / 33);
            int nhi = (c == 32) ? hi : lo + (int)((span * (c + 1)) / 33);
            lo = nlo; hi = nhi;
        }
        int pos = lo + l;
        long long x = (pos < hi) ? (is64 ? b64[pos] : (long long)bwords[pos])
                                 : 0x7fffffffffffffffLL;
        unsigned m = __ballot_sync(0xffffffffu, x < v);
        if (l == 0) bnd_s[wid] = lo + __popc(m);
    }
    // threads 96..511: stage Wk fp32 -> fp16
    if (t >= 96) {
        const float4* WkV = (const float4*)Wk;
        for (int lin = t - 96; lin < 4096; lin += 416) {
            int n = lin >> 5, j4 = lin & 31;
            float4 v = WkV[lin];
            uint2 u;
            u.x = pack_h2(v.x, v.y);
            u.y = pack_h2(v.z, v.w);
            *(uint2*)(smem + SM_WK + n * RS + j4 * 8) = u;
        }
    }
    __syncthreads();                             // bounds + Wk + bk/wm + mbars

    const int lo   = bnd_s[0];
    const int mid  = bnd_s[1];
    const int hi   = bnd_s[2];
    const int rows = hi - lo;
    const int mrel = mid - lo;                   // boundary (local row index)

    if (rows <= 0) {
        if (t < 128) {
            out[(size_t)g0 * H + t] = 0.f;
            if (g0 + 1 < B) out[(size_t)(g0 + 1) * H + t] = 0.f;
        }
        return;
    }

    const int ntiles = (rows + 127) >> 7;
    if (t == 0) issue_tma(sb, prot, lo, min(128, rows));  // tile 0

    // =============== producers: threads 256..511 ===============
    if (t >= 256) {
        const int tp = t - 256;
        for (int i = 0; i < ntiles; ++i) {
            const int b = i & 1;
            const int nvalid = min(128, rows - i * 128);
            if (i >= 2)
                MBARRIER_WAIT_PARITY(sb + SM_MB + 24 + b * 8, ((i - 2) >> 1) & 1);
            MBARRIER_WAIT_PARITY(sb + SM_MB, i & 1);
            const uint32_t ahOff = b ? SM_AH1 : SM_AH0;
#pragma unroll
            for (int it = 0; it < 16; ++it) {
                int lin = tp + it * 256;
                int r = lin >> 5, j4 = lin & 31;
                uint2 u = make_uint2(0u, 0u);
                if (r < nvalid) {
                    float4 v = *(const float4*)(smem + SM_RAW + r * 512 + j4 * 16);
                    u.x = pack_h2(v.x, v.y);
                    u.y = pack_h2(v.z, v.w);
                }
                *(uint2*)(smem + ahOff + r * RS + j4 * 8) = u;
            }
            BAR_PROD();                          // all producers done reading RAW
            if (tp == 0 && i + 1 < ntiles)
                issue_tma(sb, prot, lo + (i + 1) * 128, min(128, rows - (i + 1) * 128));
            MBARRIER_ARRIVE(sb + SM_MB + 8 + b * 8);   // full[b]
        }
        __syncthreads();                         // join final
        return;
    }

    // =============== consumers: threads 0..255 ===============
    const int mi = wid >> 2;         // 0..1 : 64-row half
    const int ni = wid & 3;          // 0..3 : 32-col group
    const uint32_t laneByte = (uint32_t)(((l & 7) + ((l >> 3) & 1) * 8) * RS + ((l >> 4) << 4));
    const uint32_t wkLane = sb + SM_WK + (uint32_t)((ni * 32 + (l >> 2)) * RS + (l & 3) * 4);

    float o0[4][2], o1[4][2];
#pragma unroll
    for (int nt = 0; nt < 4; ++nt) {
        o0[nt][0] = 0.f; o0[nt][1] = 0.f;
        o1[nt][0] = 0.f; o1[nt][1] = 0.f;
    }
    float d0 = 0.f, d1 = 0.f;

    for (int i = 0; i < ntiles; ++i) {
        const int b = i & 1;
        const int nvalid = min(128, rows - i * 128);
        const int lb = mrel - i * 128;           // rows < lb -> graph g0
        const uint32_t ahWarp = sb + (b ? SM_AH1 : SM_AH0) + (uint32_t)(mi * 64 * RS) + laneByte;
        float* scp = (float*)(smem + (b ? SM_SCP1 : SM_SCP0));
        float* e_s = (float*)(smem + (b ? SM_ES1 : SM_ES0));

        MBARRIER_WAIT_PARITY(sb + SM_MB + 8 + b * 8, (i >> 1) & 1);

        // ---- MMA: A via ldsm, B via LDS from WK ----
        float acc[4][4][4];
#pragma unroll
        for (int mt = 0; mt < 4; ++mt)
#pragma unroll
            for (int nt = 0; nt < 4; ++nt)
#pragma unroll
                for (int i2 = 0; i2 < 4; ++i2) acc[mt][nt][i2] = 0.f;

#pragma unroll
        for (int kt = 0; kt < 8; ++kt) {
            uint32_t bb[4][2];
#pragma unroll
            for (int nt = 0; nt < 4; ++nt) {
                const char* baddr = smem + (wkLane - sb) + nt * 8 * RS + kt * 32;
                bb[nt][0] = *(const uint32_t*)(baddr);
                bb[nt][1] = *(const uint32_t*)(baddr + 16);
            }
#pragma unroll
            for (int mt = 0; mt < 4; ++mt) {
                uint32_t ah[4];
                ldsm4(ah, ahWarp + (uint32_t)(mt * 16 * RS + kt * 32));
#pragma unroll
                for (int nt = 0; nt < 4; ++nt)
                    mma16816(acc[mt][nt], ah, bb[nt]);
            }
        }
        MBARRIER_ARRIVE(sb + SM_MB + 24 + b * 8);    // empty[b]

        // ---- relu + bias; score partials ----
#pragma unroll
        for (int mt = 0; mt < 4; ++mt) {
            float s0 = 0.f, s1 = 0.f;
#pragma unroll
            for (int nt = 0; nt < 4; ++nt) {
                int c = ni * 32 + nt * 8 + 2 * (l & 3);
                float2 bkv = *(const float2*)(bk_s + c);
                float2 wmv = *(const float2*)(wm_s + c);
                acc[mt][nt][0] = fmaxf(acc[mt][nt][0] + bkv.x, 0.f);
                acc[mt][nt][1] = fmaxf(acc[mt][nt][1] + bkv.y, 0.f);
                acc[mt][nt][2] = fmaxf(acc[mt][nt][2] + bkv.x, 0.f);
                acc[mt][nt][3] = fmaxf(acc[mt][nt][3] + bkv.y, 0.f);
                s0 = fmaf(acc[mt][nt][0], wmv.x, s0);
                s0 = fmaf(acc[mt][nt][1], wmv.y, s0);
                s1 = fmaf(acc[mt][nt][2], wmv.x, s1);
                s1 = fmaf(acc[mt][nt][3], wmv.y, s1);
            }
#pragma unroll
            for (int o = 1; o <= 2; o <<= 1) {
                s0 += __shfl_xor_sync(0xffffffffu, s0, o);
                s1 += __shfl_xor_sync(0xffffffffu, s1, o);
            }
            if ((l & 3) == 0) {
                int row = mi * 64 + mt * 16 + (l >> 2);
                scp[ni * 128 + row]     = s0;
                scp[ni * 128 + row + 8] = s1;
            }
        }
        BAR_CONS();                              // scp ready

        if (t < 128) {
            float s = scp[t] + scp[128 + t] + scp[256 + t] + scp[384 + t];
            float e = (t < nvalid) ? __expf(s) : 0.f;
            e_s[t] = e;
            if (t < lb) d0 += e; else d1 += e;
        }
        BAR_CONS();                              // e_s ready

        // ---- o accumulation into banks ----
        if (lb >= nvalid) {                      // all graph g0
#pragma unroll
            for (int mt = 0; mt < 4; ++mt) {
                int row = mi * 64 + mt * 16 + (l >> 2);
                float elo = e_s[row], ehi = e_s[row + 8];
#pragma unroll
                for (int nt = 0; nt < 4; ++nt) {
                    o0[nt][0] = fmaf(elo, acc[mt][nt][0], o0[nt][0]);
                    o0[nt][0] = fmaf(ehi, acc[mt][nt][2], o0[nt][0]);
                    o0[nt][1] = fmaf(elo, acc[mt][nt][1], o0[nt][1]);
                    o0[nt][1] = fmaf(ehi, acc[mt][nt][3], o0[nt][1]);
                }
            }
        } else if (lb <= 0) {                    // all graph g1
#pragma unroll
            for (int mt = 0; mt < 4; ++mt) {
                int row = mi * 64 + mt * 16 + (l >> 2);
                float elo = e_s[row], ehi = e_s[row + 8];
#pragma unroll
                for (int nt = 0; nt < 4; ++nt) {
                    o1[nt][0] = fmaf(elo, acc[mt][nt][0], o1[nt][0]);
                    o1[nt][0] = fmaf(ehi, acc[mt][nt][2], o1[nt][0]);
                    o1[nt][1] = fmaf(elo, acc[mt][nt][1], o1[nt][1]);
                    o1[nt][1] = fmaf(ehi, acc[mt][nt][3], o1[nt][1]);
                }
            }
        } else {                                 // boundary tile
#pragma unroll
            for (int mt = 0; mt < 4; ++mt) {
                int row = mi * 64 + mt * 16 + (l >> 2);
                float e = e_s[row], e2 = e_s[row + 8];
                float eA0 = (row < lb) ? e : 0.f,      eA1 = e - eA0;
                float eB0 = (row + 8 < lb) ? e2 : 0.f, eB1 = e2 - eB0;
#pragma unroll
                for (int nt = 0; nt < 4; ++nt) {
                    o0[nt][0] = fmaf(eA0, acc[mt][nt][0], o0[nt][0]);
                    o0[nt][0] = fmaf(eB0, acc[mt][nt][2], o0[nt][0]);
                    o0[nt][1] = fmaf(eA0, acc[mt][nt][1], o0[nt][1]);
                    o0[nt][1] = fmaf(eB0, acc[mt][nt][3], o0[nt][1]);
                    o1[nt][0] = fmaf(eA1, acc[mt][nt][0], o1[nt][0]);
                    o1[nt][0] = fmaf(eB1, acc[mt][nt][2], o1[nt][0]);
                    o1[nt][1] = fmaf(eA1, acc[mt][nt][1], o1[nt][1]);
                    o1[nt][1] = fmaf(eB1, acc[mt][nt][3], o1[nt][1]);
                }
            }
        }
    }

    // ---- final reductions & output (consumers; producers already at sync) ----
    {
        float* op0 = (float*)(smem + SM_SCP0);   // reuse as o_part bank0 [2][128]
        float* op1 = (float*)(smem + SM_SCP1);   // bank1
#pragma unroll
        for (int nt = 0; nt < 4; ++nt)
#pragma unroll
            for (int o = 4; o <= 16; o <<= 1) {
                o0[nt][0] += __shfl_xor_sync(0xffffffffu, o0[nt][0], o);
                o0[nt][1] += __shfl_xor_sync(0xffffffffu, o0[nt][1], o);
                o1[nt][0] += __shfl_xor_sync(0xffffffffu, o1[nt][0], o);
                o1[nt][1] += __shfl_xor_sync(0xffffffffu, o1[nt][1], o);
            }
        BAR_CONS();                              // scp buffers free for reuse
        if ((l >> 2) == 0) {
#pragma unroll
            for (int nt = 0; nt < 4; ++nt) {
                int c = ni * 32 + nt * 8 + 2 * l;
                op0[mi * 128 + c]     = o0[nt][0];
                op0[mi * 128 + c + 1] = o0[nt][1];
                op1[mi * 128 + c]     = o1[nt][0];
                op1[mi * 128 + c + 1] = o1[nt][1];
            }
        }
        if (t < 128) {
#pragma unroll
            for (int o = 16; o; o >>= 1) {
                d0 += __shfl_xor_sync(0xffffffffu, d0, o);
                d1 += __shfl_xor_sync(0xffffffffu, d1, o);
            }
            if (l == 0) { red_s[wid] = d0; red_s[4 + wid] = d1; }
        }
        BAR_CONS();
        if (t < 128) {
            float dd0 = red_s[0] + red_s[1] + red_s[2] + red_s[3];
            float dd1 = red_s[4] + red_s[5] + red_s[6] + red_s[7];
            float oo0 = op0[t] + op0[128 + t];
            float oo1 = op1[t] + op1[128 + t];
            out[(size_t)g0 * H + t] = (dd0 > 0.f) ? (oo0 / dd0) : 0.f;
            if (g0 + 1 < B)
                out[(size_t)(g0 + 1) * H + t] = (dd1 > 0.f) ? (oo1 / dd1) : 0.f;
        }
    }
    __syncthreads();                             // join producers
}

// ---------------------------------------------------------------------------
extern "C" void kernel_launch(void* const* d_in, const int* in_sizes, int n_in,
                              void* d_out, int out_size) {
    const float* mol   = (const float*)d_in[0];
    const float* prot  = (const float*)d_in[1];
    const int*   batch = (const int*)d_in[2];
    const float* Wq    = (const float*)d_in[3];
    const float* bq    = (const float*)d_in[4];
    const float* Wk    = (const float*)d_in[5];
    const float* bk    = (const float*)d_in[6];
    const float* Wm    = (const float*)d_in[7];
    float* out = (float*)d_out;

    int B = in_sizes[0] / H;   // 256
    int N = in_sizes[1] / H;   // 262144
    int BA = (B + 1) / 2;      // attn blocks (2 graphs each)
    int qb = (B + QGPB - 1) / QGPB;

    cudaFuncSetAttribute(fused_kernel, cudaFuncAttributeMaxDynamicSharedMemorySize, SM_TOTAL);
    fused_kernel<<<BA + qb, THREADS, SM_TOTAL>>>(
        prot, Wk, bk, Wm, batch, mol, Wq, bq, out, N, B, BA);
}